// round 1
// baseline (speedup 1.0000x reference)
#include <cuda_runtime.h>
#include <math.h>

// MSCALE = (0.1 * ln(4.0) + 1.0) * 1.0
#define MSCALE 1.1386294361119891f

// Output layout: [cos (1,L,128) | sin (1,L,128)], float32.
// cos[l][d] = cos[l][d+64] = cosf(pos_ids[l % w_d] * inv_freq[d]) * MSCALE
// Each thread handles one row l and 4 consecutive d values (d = 4*q .. 4*q+3),
// writing 4x float4 (cos lo-half, cos hi-half, sin lo, sin hi), all coalesced.
__global__ void __launch_bounds__(256) yarn_cos_sin_kernel(
    const int* __restrict__ pos_ids,
    const float* __restrict__ inv_freq,
    const float* __restrict__ wav,
    float* __restrict__ out,
    int L)
{
    int idx = blockIdx.x * blockDim.x + threadIdx.x;  // over L * 16
    if (idx >= L * 16) return;

    int l  = idx >> 4;          // row (position)
    int dq = (idx & 15) << 2;   // base d in [0,64), step 4

    float4 cv, sv;
    float* cp = reinterpret_cast<float*>(&cv);
    float* sp = reinterpret_cast<float*>(&sv);

#pragma unroll
    for (int k = 0; k < 4; k++) {
        int d = dq + k;
        int w = (int)__ldg(&wav[d]);
        int p = l % w;                           // index into position_ids
        float pos = (float)__ldg(&pos_ids[p]);
        float f = pos * __ldg(&inv_freq[d]);
        float s, c;
        sincosf(f, &s, &c);
        cp[k] = c * MSCALE;
        sp[k] = s * MSCALE;
    }

    float* cos_base = out;
    float* sin_base = out + (size_t)L * 128;
    size_t base = (size_t)l * 128 + dq;

    *reinterpret_cast<float4*>(cos_base + base)      = cv;
    *reinterpret_cast<float4*>(cos_base + base + 64) = cv;
    *reinterpret_cast<float4*>(sin_base + base)      = sv;
    *reinterpret_cast<float4*>(sin_base + base + 64) = sv;
}

extern "C" void kernel_launch(void* const* d_in, const int* in_sizes, int n_in,
                              void* d_out, int out_size) {
    // metadata order: x (unused), position_ids, r_inv_freq, r_wavelengths
    const int*   pos_ids  = (const int*)d_in[1];
    const float* inv_freq = (const float*)d_in[2];
    const float* wav      = (const float*)d_in[3];
    float* out = (float*)d_out;

    int L = in_sizes[1];  // 16384

    int total = L * 16;
    int threads = 256;
    int blocks = (total + threads - 1) / threads;
    yarn_cos_sin_kernel<<<blocks, threads>>>(pos_ids, inv_freq, wav, out, L);
}

// round 2
// speedup vs baseline: 1.0332x; 1.0332x over previous
#include <cuda_runtime.h>
#include <math.h>

// MSCALE = (0.1 * ln(4.0) + 1.0) * 1.0
#define MSCALE 1.1386294361119891f

// Output layout: [cos (1,L,128) | sin (1,L,128)], float32.
// cos[l][d] = cos[l][d+64] = cos(pos_ids[l % w_d] * inv_freq[d]) * MSCALE
//
// Instruction-latency-bound kernel (per R1 ncu: DRAM 0.1%, all pipes <15%,
// issue 43%): the cost was precise sincosf (~60 instr) + emulated IDIV (~16).
// This version uses MUFU sin/cos (args bounded in [0,2pi), abs err ~1e-6,
// threshold is 1e-3) and a float fast-reciprocal modulo with exact-fma
// remainder + one-step correction (l, q*w < 2^24 so all fp32-exact).
__global__ void __launch_bounds__(256) yarn_cos_sin_kernel(
    const int* __restrict__ pos_ids,
    const float* __restrict__ inv_freq,
    const float* __restrict__ wav,
    float* __restrict__ out,
    int L)
{
    int idx = blockIdx.x * blockDim.x + threadIdx.x;  // over L * 16
    if (idx >= L * 16) return;

    int l  = idx >> 4;          // row (position)
    int dq = (idx & 15) << 2;   // base d in [0,64), step 4
    float lf = (float)l;

    // tiny tables, vector loads (dq is 4-aligned)
    float4 w4  = *reinterpret_cast<const float4*>(wav + dq);
    float4 if4 = *reinterpret_cast<const float4*>(inv_freq + dq);
    const float* wp  = reinterpret_cast<const float*>(&w4);
    const float* ifp = reinterpret_cast<const float*>(&if4);

    float4 cv, sv;
    float* cp = reinterpret_cast<float*>(&cv);
    float* sp = reinterpret_cast<float*>(&sv);

#pragma unroll
    for (int k = 0; k < 4; k++) {
        float wf = wp[k];                     // integer-valued wavelength
        // fast modulo: r = l - w * trunc(l/w), exact fma, then fix off-by-one
        float q = truncf(__fdividef(lf, wf));
        float r = fmaf(-q, wf, lf);
        r = (r < 0.0f)  ? r + wf : r;
        r = (r >= wf)   ? r - wf : r;
        int p = (int)r;

        float pos = (float)__ldg(&pos_ids[p]);   // L1/L2-resident gather
        float f = pos * ifp[k];                  // in [0, 2*pi)
        float s, c;
        __sincosf(f, &s, &c);                    // MUFU.SIN / MUFU.COS
        cp[k] = c * MSCALE;
        sp[k] = s * MSCALE;
    }

    float* cos_base = out;
    float* sin_base = out + (size_t)L * 128;
    size_t base = (size_t)l * 128 + dq;

    *reinterpret_cast<float4*>(cos_base + base)      = cv;
    *reinterpret_cast<float4*>(cos_base + base + 64) = cv;
    *reinterpret_cast<float4*>(sin_base + base)      = sv;
    *reinterpret_cast<float4*>(sin_base + base + 64) = sv;
}

extern "C" void kernel_launch(void* const* d_in, const int* in_sizes, int n_in,
                              void* d_out, int out_size) {
    // metadata order: x (unused), position_ids, r_inv_freq, r_wavelengths
    const int*   pos_ids  = (const int*)d_in[1];
    const float* inv_freq = (const float*)d_in[2];
    const float* wav      = (const float*)d_in[3];
    float* out = (float*)d_out;

    int L = in_sizes[1];  // 16384

    int total = L * 16;
    int threads = 256;
    int blocks = (total + threads - 1) / threads;
    yarn_cos_sin_kernel<<<blocks, threads>>>(pos_ids, inv_freq, wav, out, L);
}